// round 1
// baseline (speedup 1.0000x reference)
#include <cuda_runtime.h>
#include <cuda_bf16.h>

#define N_NODES 20000
#define E_EDGES 640000
#define E_TOT   (E_EDGES + N_NODES)   // with self loops
#define IN_F    256
#define HEADS   8
#define HF      64
#define OUTF    32
#define NEG_SLOPE 0.2f

// ------------------- scratch (static device globals; no allocs) -------------------
__device__ float g_h1[(size_t)N_NODES * HEADS * HF];    // 20000*512
__device__ float g_h1m[(size_t)N_NODES * HF];           // 20000*64
__device__ float g_h2[(size_t)N_NODES * HEADS * OUTF];  // 20000*256
__device__ float g_as1[N_NODES * HEADS];
__device__ float g_ad1[N_NODES * HEADS];
__device__ float g_as2[N_NODES * HEADS];
__device__ float g_ad2[N_NODES * HEADS];
__device__ int   g_deg[N_NODES];
__device__ int   g_off[N_NODES + 1];
__device__ int   g_cur[N_NODES];
__device__ int   g_csr[E_TOT];

// ------------------- CSR build -------------------
__global__ void count_kernel(const int* __restrict__ dst, int* __restrict__ deg) {
    int i = blockIdx.x * blockDim.x + threadIdx.x;
    if (i < E_EDGES) {
        atomicAdd(&deg[dst[i]], 1);
    } else if (i < E_TOT) {
        atomicAdd(&deg[i - E_EDGES], 1);   // self loop
    }
}

__global__ void scan_kernel(const int* __restrict__ deg, int* __restrict__ off,
                            int* __restrict__ cur) {
    const int T = 1024;
    const int n = N_NODES;
    int t = threadIdx.x;
    const int chunk = (n + T - 1) / T;   // 20
    int local[32];
    int start = t * chunk;
    int sum = 0;
    #pragma unroll
    for (int i = 0; i < chunk; i++) {
        int idx = start + i;
        int v = (idx < n) ? deg[idx] : 0;
        local[i] = sum;
        sum += v;
    }
    __shared__ int s[T];
    s[t] = sum;
    __syncthreads();
    for (int d = 1; d < T; d <<= 1) {
        int v = (t >= d) ? s[t - d] : 0;
        __syncthreads();
        s[t] += v;
        __syncthreads();
    }
    int base = (t > 0) ? s[t - 1] : 0;
    #pragma unroll
    for (int i = 0; i < chunk; i++) {
        int idx = start + i;
        if (idx < n) {
            int o = base + local[i];
            off[idx] = o;
            cur[idx] = o;
        }
    }
    if (t == T - 1) off[n] = s[T - 1];
}

__global__ void scatter_kernel(const int* __restrict__ src, const int* __restrict__ dst,
                               int* __restrict__ cur, int* __restrict__ csr) {
    int i = blockIdx.x * blockDim.x + threadIdx.x;
    if (i < E_EDGES) {
        int d = dst[i];
        int p = atomicAdd(&cur[d], 1);
        csr[p] = src[i];
    } else if (i < E_TOT) {
        int nd = i - E_EDGES;
        int p = atomicAdd(&cur[nd], 1);
        csr[p] = nd;
    }
}

// ------------------- GEMM: C[M,Nn] = A[M,K] @ B[K,Nn] -------------------
// BM=64, BN=64, BK=16, 256 threads, 4x4 per thread.
__global__ __launch_bounds__(256)
void gemm_kernel(const float* __restrict__ A, const float* __restrict__ B,
                 float* __restrict__ C, int M, int Nn, int K) {
    __shared__ float As[16][64];
    __shared__ float Bs[16][64];
    int bm = blockIdx.y * 64;
    int bn = blockIdx.x * 64;
    int tx = threadIdx.x % 16;
    int ty = threadIdx.x / 16;
    float acc[4][4] = {};

    for (int k0 = 0; k0 < K; k0 += 16) {
        // load A tile (64x16) — 1024 elems / 256 threads = 4 each
        #pragma unroll
        for (int t = threadIdx.x; t < 64 * 16; t += 256) {
            int m = t >> 4, kk = t & 15;
            int gm = bm + m;
            As[kk][m] = (gm < M) ? A[(size_t)gm * K + k0 + kk] : 0.0f;
        }
        // load B tile (16x64)
        #pragma unroll
        for (int t = threadIdx.x; t < 16 * 64; t += 256) {
            int kk = t >> 6, nn = t & 63;
            Bs[kk][nn] = B[(size_t)(k0 + kk) * Nn + bn + nn];
        }
        __syncthreads();
        #pragma unroll
        for (int kk = 0; kk < 16; kk++) {
            float4 a4 = *reinterpret_cast<const float4*>(&As[kk][ty * 4]);
            float4 b4 = *reinterpret_cast<const float4*>(&Bs[kk][tx * 4]);
            float a[4] = {a4.x, a4.y, a4.z, a4.w};
            float b[4] = {b4.x, b4.y, b4.z, b4.w};
            #pragma unroll
            for (int i = 0; i < 4; i++)
                #pragma unroll
                for (int j = 0; j < 4; j++)
                    acc[i][j] += a[i] * b[j];
        }
        __syncthreads();
    }
    #pragma unroll
    for (int i = 0; i < 4; i++) {
        int gm = bm + ty * 4 + i;
        if (gm < M) {
            float4 v = make_float4(acc[i][0], acc[i][1], acc[i][2], acc[i][3]);
            *reinterpret_cast<float4*>(&C[(size_t)gm * Nn + bn + tx * 4]) = v;
        }
    }
}

// ------------------- attention logits: asrc[n,h], adst[n,h] -------------------
__global__ void logits_kernel(const float* __restrict__ h, const float* __restrict__ att_src,
                              const float* __restrict__ att_dst, float* __restrict__ asrc,
                              float* __restrict__ adst, int C) {
    int gtid = blockIdx.x * blockDim.x + threadIdx.x;
    int w = gtid >> 5;
    int lane = gtid & 31;
    if (w >= N_NODES * HEADS) return;
    int hh = w % HEADS;
    const float* hp = h + (size_t)w * C;
    float s1 = 0.f, s2 = 0.f;
    for (int c = lane; c < C; c += 32) {
        float v = hp[c];
        s1 += v * att_src[hh * C + c];
        s2 += v * att_dst[hh * C + c];
    }
    #pragma unroll
    for (int o = 16; o > 0; o >>= 1) {
        s1 += __shfl_down_sync(0xffffffffu, s1, o);
        s2 += __shfl_down_sync(0xffffffffu, s2, o);
    }
    if (lane == 0) {
        asrc[w] = s1;
        adst[w] = s2;
    }
}

// ------------------- GAT aggregation: one CTA per dst node, one warp per head -----
// Pass 1: exact segment max per (node,head). Pass 2: fused exp-sum + weighted
// accumulation of gathered source features. Then head-mean + bias (+relu).
template <int C, bool RELU>
__global__ __launch_bounds__(256)
void aggregate_kernel(const float* __restrict__ h, const float* __restrict__ asrc,
                      const float* __restrict__ adst, const int* __restrict__ off,
                      const int* __restrict__ csr, const float* __restrict__ bias,
                      float* __restrict__ out) {
    constexpr int V = C / 32;   // floats per lane (2 for C=64, 1 for C=32)
    int node = blockIdx.x;
    int warp = threadIdx.x >> 5;   // head
    int lane = threadIdx.x & 31;

    float ad = adst[node * HEADS + warp];
    int beg = off[node];
    int end = off[node + 1];

    // pass 1: max (all lanes compute same value; scalar loads broadcast)
    float m = -3.0e38f;
    #pragma unroll 4
    for (int j = beg; j < end; j++) {
        int s = __ldg(&csr[j]);
        float e = __ldg(&asrc[s * HEADS + warp]) + ad;
        e = (e >= 0.f) ? e : NEG_SLOPE * e;
        m = fmaxf(m, e);
    }

    // pass 2: exp-sum + weighted gather
    float den = 0.f;
    float acc[V];
    #pragma unroll
    for (int v = 0; v < V; v++) acc[v] = 0.f;

    #pragma unroll 2
    for (int j = beg; j < end; j++) {
        int s = __ldg(&csr[j]);
        float e = __ldg(&asrc[s * HEADS + warp]) + ad;
        e = (e >= 0.f) ? e : NEG_SLOPE * e;
        float ex = __expf(e - m);
        den += ex;
        const float* hp = h + ((size_t)s * HEADS + warp) * C;
        #pragma unroll
        for (int v = 0; v < V; v++)
            acc[v] += ex * __ldg(&hp[lane + v * 32]);
    }

    __shared__ float sacc[HEADS][C];
    float inv = 1.0f / den;
    #pragma unroll
    for (int v = 0; v < V; v++)
        sacc[warp][lane + v * 32] = acc[v] * inv;
    __syncthreads();

    // head mean + bias (+relu): threads 0..C-1
    if (threadIdx.x < C) {
        float sum = 0.f;
        #pragma unroll
        for (int hh = 0; hh < HEADS; hh++) sum += sacc[hh][threadIdx.x];
        sum = sum * (1.0f / HEADS) + bias[threadIdx.x];
        if (RELU) sum = fmaxf(sum, 0.f);
        out[(size_t)node * C + threadIdx.x] = sum;
    }
}

// ------------------- launch -------------------
extern "C" void kernel_launch(void* const* d_in, const int* in_sizes, int n_in,
                              void* d_out, int out_size) {
    const float* x        = (const float*)d_in[0];
    const int*   ei       = (const int*)  d_in[1];   // [2, E]
    const float* W1       = (const float*)d_in[2];
    const float* att_src1 = (const float*)d_in[3];
    const float* att_dst1 = (const float*)d_in[4];
    const float* b1       = (const float*)d_in[5];
    const float* W2       = (const float*)d_in[6];
    const float* att_src2 = (const float*)d_in[7];
    const float* att_dst2 = (const float*)d_in[8];
    const float* b2       = (const float*)d_in[9];
    float* out = (float*)d_out;

    const int* src = ei;
    const int* dst = ei + E_EDGES;

    float *h1, *h1m, *h2, *as1, *ad1, *as2, *ad2;
    int *deg, *off, *cur, *csr;
    cudaGetSymbolAddress((void**)&h1,  g_h1);
    cudaGetSymbolAddress((void**)&h1m, g_h1m);
    cudaGetSymbolAddress((void**)&h2,  g_h2);
    cudaGetSymbolAddress((void**)&as1, g_as1);
    cudaGetSymbolAddress((void**)&ad1, g_ad1);
    cudaGetSymbolAddress((void**)&as2, g_as2);
    cudaGetSymbolAddress((void**)&ad2, g_ad2);
    cudaGetSymbolAddress((void**)&deg, g_deg);
    cudaGetSymbolAddress((void**)&off, g_off);
    cudaGetSymbolAddress((void**)&cur, g_cur);
    cudaGetSymbolAddress((void**)&csr, g_csr);

    cudaStream_t st = 0;

    // CSR build
    cudaMemsetAsync(deg, 0, N_NODES * sizeof(int), st);
    {
        int threads = 256, blocks = (E_TOT + threads - 1) / threads;
        count_kernel<<<blocks, threads, 0, st>>>(dst, deg);
        scan_kernel<<<1, 1024, 0, st>>>(deg, off, cur);
        scatter_kernel<<<blocks, threads, 0, st>>>(src, dst, cur, csr);
    }

    // Layer 1
    {
        dim3 grid(HEADS * HF / 64, (N_NODES + 63) / 64);
        gemm_kernel<<<grid, 256, 0, st>>>(x, W1, h1, N_NODES, HEADS * HF, IN_F);
        int total = N_NODES * HEADS * 32;
        logits_kernel<<<(total + 255) / 256, 256, 0, st>>>(h1, att_src1, att_dst1, as1, ad1, HF);
        aggregate_kernel<HF, true><<<N_NODES, 256, 0, st>>>(h1, as1, ad1, off, csr, b1, h1m);
    }

    // Layer 2
    {
        dim3 grid(HEADS * OUTF / 64, (N_NODES + 63) / 64);
        gemm_kernel<<<grid, 256, 0, st>>>(h1m, W2, h2, N_NODES, HEADS * OUTF, HF);
        int total = N_NODES * HEADS * 32;
        logits_kernel<<<(total + 255) / 256, 256, 0, st>>>(h2, att_src2, att_dst2, as2, ad2, OUTF);
        aggregate_kernel<OUTF, false><<<N_NODES, 256, 0, st>>>(h2, as2, ad2, off, csr, b2, out);
    }
}